// round 10
// baseline (speedup 1.0000x reference)
#include <cuda_runtime.h>
#include <cuda_bf16.h>
#include <math.h>
#include <stdint.h>

// Problem constants
#define B_SZ 64
#define D_SZ 2048
#define H_SZ 256

// GEMM: CTA = 128 M x 256 N, K streamed in 16 slices of k16.
#define TILE_M 128
#define NDT    (D_SZ / TILE_M)   // 16
#define NKS    16                // k16 slices
#define AS_STR 12                // slice row stride in b32 (8 data + 4 pad;
                                 // 48B rows: 16B-aligned AND conflict-free)
#define AS_B32 (TILE_M * AS_STR)     // 1536 per buffer
#define BS_B32 (H_SZ  * AS_STR)      // 3072 per buffer
#define DYN_SMEM ((3 * AS_B32 + 4 * BS_B32) * 4)   // 67584 bytes

// Scratch (__device__ globals: allocation-free rule)
__device__ float    g_scores [B_SZ * D_SZ];
__device__ float    g_bias   [B_SZ * H_SZ];
__device__ float    g_partial[B_SZ * 16 * H_SZ];
__device__ uint32_t g_w1bf   [H_SZ * H_SZ / 2];   // W1 as bf16x2 pairs [n][128]

// ---------------- helpers ----------------
__device__ __forceinline__ uint32_t smem_u32(const void* p) {
    uint32_t a;
    asm("{ .reg .u64 t; cvta.to.shared.u64 t, %1; cvt.u32.u64 %0, t; }" : "=r"(a) : "l"(p));
    return a;
}
__device__ __forceinline__ float tanh_fast(float x) {
    float y;
    asm("tanh.approx.f32 %0, %1;" : "=f"(y) : "f"(x));
    return y;
}
__device__ __forceinline__ uint32_t pack_bf16(float lo, float hi) {
    uint32_t r;
    asm("cvt.rn.bf16x2.f32 %0, %1, %2;" : "=r"(r) : "f"(hi), "f"(lo));
    return r;
}
__device__ __forceinline__ void cp16(uint32_t dst, const void* src) {
    asm volatile("cp.async.cg.shared.global [%0], [%1], 16;" :: "r"(dst), "l"(src));
}
__device__ __forceinline__ void mma_bf16(float* d, const uint32_t* a, const uint32_t* b) {
    asm volatile(
        "mma.sync.aligned.m16n8k16.row.col.f32.bf16.bf16.f32 "
        "{%0,%1,%2,%3}, {%4,%5,%6,%7}, {%8,%9}, {%0,%1,%2,%3};"
        : "+f"(d[0]), "+f"(d[1]), "+f"(d[2]), "+f"(d[3])
        : "r"(a[0]), "r"(a[1]), "r"(a[2]), "r"(a[3]), "r"(b[0]), "r"(b[1]));
}

// ---------------------------------------------------------------------------
// Kernel 0: fused prep. Blocks 0..127: W1 fp32 -> bf16x2. Blocks 128..191:
// bias c[b][h] = W2@ctx + b2 + W3@hid.  grid = 192, block = 256.
// ---------------------------------------------------------------------------
__global__ void prep_kernel(const float* __restrict__ W1,
                            const float* __restrict__ ctx,
                            const float* __restrict__ hid,
                            const float* __restrict__ W2,
                            const float* __restrict__ b2,
                            const float* __restrict__ W3) {
    if (blockIdx.x < 128) {
        int i = blockIdx.x * 256 + threadIdx.x;
        float2 v = reinterpret_cast<const float2*>(W1)[i];
        g_w1bf[i] = pack_bf16(v.x, v.y);
        return;
    }
    int b = blockIdx.x - 128;
    int h = threadIdx.x;
    __shared__ float cs[H_SZ];
    __shared__ float hs[H_SZ];
    cs[h] = ctx[b * H_SZ + h];
    hs[h] = hid[b * H_SZ + h];
    __syncthreads();

    const float4* w2r = reinterpret_cast<const float4*>(W2 + (size_t)h * H_SZ);
    const float4* w3r = reinterpret_cast<const float4*>(W3 + (size_t)h * H_SZ);
    float acc = b2[h];
    #pragma unroll 8
    for (int k4 = 0; k4 < H_SZ / 4; k4++) {
        float4 a = w2r[k4], c = w3r[k4];
        int k = k4 * 4;
        acc += cs[k]*a.x + cs[k+1]*a.y + cs[k+2]*a.z + cs[k+3]*a.w;
        acc += hs[k]*c.x + hs[k+1]*c.y + hs[k+2]*c.z + hs[k+3]*c.w;
    }
    g_bias[b * H_SZ + h] = acc;
}

// ---------------------------------------------------------------------------
// Kernel 1: software-pipelined bf16 mma GEMM (Q @ W1^T) + fused tanh/W4 ->
// raw scores. 512 threads, 16 warps (wm = wid>>3, wn = wid&7; warp tile
// 64x32). A: LDG float4 + cvt + STS, 3-buffer ring. B: cp.async from
// g_w1bf, 4-buffer ring. Prefetch issued AFTER the barrier (no WAR race);
// wait counts retire slice s before its compute.
// ---------------------------------------------------------------------------
__global__ void __launch_bounds__(512)
gemm_score_bf16(const float* __restrict__ Q,
                const float* __restrict__ W4,
                const float* __restrict__ b4) {
    extern __shared__ uint32_t ring[];
    uint32_t* As = ring;                   // [3][AS_B32]
    uint32_t* Bs = ring + 3 * AS_B32;      // [4][BS_B32]
    __shared__ float cs[H_SZ];
    __shared__ float w4s[H_SZ];
    __shared__ float spart[TILE_M][8];

    const int b    = blockIdx.y;
    const int dt   = blockIdx.x;
    const int tid  = threadIdx.x;
    const int wid  = tid >> 5;
    const int lane = tid & 31;
    const int wm   = wid >> 3;         // 0..1
    const int wn   = wid & 7;          // 0..7
    const int gq   = lane >> 2;        // 0..7
    const int tq   = lane & 3;         // 0..3

    if (tid < H_SZ) {
        cs[tid]  = g_bias[b * H_SZ + tid];
        w4s[tid] = W4[tid];
    }

    const uint32_t bsm = smem_u32(Bs);
    // B slice loader: 1 cp16 per thread (n = tid>>1, chunk = tid&1)
    const int bn = tid >> 1, bc = tid & 1;
    const char* bsrc0 = reinterpret_cast<const char*>(g_w1bf) + bn * 512 + bc * 16;
    const uint32_t bdst0 = bsm + (uint32_t)(bn * AS_STR + bc * 4) * 4;  // 48bn+16bc

    // A slice loader: 1 float4 per thread. Slice s, thread (ar, af) loads
    // global float4 (ar*64 + 4*s + af) -> slice-row ar, b32 pair 2*af.
    const int ar = tid >> 2, af = tid & 3;
    const float4* qg = reinterpret_cast<const float4*>(
        Q + ((size_t)b * D_SZ + (size_t)dt * TILE_M) * H_SZ);
    const float4* asrc0 = qg + ar * 64 + af;       // + 4*s for slice s
    uint32_t* adst0 = As + ar * AS_STR + af * 2;

    // Prologue: B slices 0,1,2 (3 cp.async groups); A slices 0,1 direct.
    #pragma unroll
    for (int s = 0; s < 3; s++) {
        cp16(bdst0 + (uint32_t)(s * BS_B32 * 4), bsrc0 + s * 32);
        asm volatile("cp.async.commit_group;" ::: "memory");
    }
    #pragma unroll
    for (int s = 0; s < 2; s++) {
        float4 v = asrc0[4 * s];
        uint32_t* d = adst0 + s * AS_B32;
        d[0] = pack_bf16(v.x, v.y);
        d[1] = pack_bf16(v.z, v.w);
    }

    float acc[4][4][4];
    #pragma unroll
    for (int i = 0; i < 4; i++)
        #pragma unroll
        for (int j = 0; j < 4; j++)
            #pragma unroll
            for (int r = 0; r < 4; r++) acc[i][j][r] = 0.0f;

    const int aOff[4] = { (wm*64 + 0*16 + gq) * AS_STR + tq,
                          (wm*64 + 1*16 + gq) * AS_STR + tq,
                          (wm*64 + 2*16 + gq) * AS_STR + tq,
                          (wm*64 + 3*16 + gq) * AS_STR + tq };
    const int bOff[4] = { (wn*32 + 0*8 + gq) * AS_STR + tq,
                          (wn*32 + 1*8 + gq) * AS_STR + tq,
                          (wn*32 + 2*8 + gq) * AS_STR + tq,
                          (wn*32 + 3*8 + gq) * AS_STR + tq };

    #pragma unroll 1
    for (int s = 0; s < NKS; s++) {
        // Retire slice s: pending groups are a subset of {s, s+1, s+2}.
        if (s < NKS - 2)
            asm volatile("cp.async.wait_group 2;" ::: "memory");
        else if (s == NKS - 2)
            asm volatile("cp.async.wait_group 1;" ::: "memory");
        else
            asm volatile("cp.async.wait_group 0;" ::: "memory");
        __syncthreads();   // all threads' slice-s data visible; old readers done

        // Prefetch B slice s+3 (ring mod 4) — safe now, post-barrier.
        if (s + 3 < NKS) {
            cp16(bdst0 + (uint32_t)(((s + 3) & 3) * BS_B32 * 4), bsrc0 + (s + 3) * 32);
            asm volatile("cp.async.commit_group;" ::: "memory");
        }
        // Prefetch A slice s+2 into registers
        float4 av;
        const bool doA = (s + 2 < NKS);
        if (doA) av = asrc0[4 * (s + 2)];

        // Compute slice s
        {
            const uint32_t* Asl = As + (s % 3) * AS_B32;
            const uint32_t* Bsl = Bs + (s & 3) * BS_B32;
            uint32_t a[4][4], bb[4][2];
            #pragma unroll
            for (int ms = 0; ms < 4; ms++) {
                a[ms][0] = Asl[aOff[ms]];
                a[ms][1] = Asl[aOff[ms] + 8 * AS_STR];
                a[ms][2] = Asl[aOff[ms] + 4];
                a[ms][3] = Asl[aOff[ms] + 8 * AS_STR + 4];
            }
            #pragma unroll
            for (int ns = 0; ns < 4; ns++) {
                bb[ns][0] = Bsl[bOff[ns]];
                bb[ns][1] = Bsl[bOff[ns] + 4];
            }
            #pragma unroll
            for (int ms = 0; ms < 4; ms++)
                #pragma unroll
                for (int ns = 0; ns < 4; ns++)
                    mma_bf16(acc[ms][ns], a[ms], bb[ns]);
        }

        // Store prefetched A slice into buffer (s+2)%3; readers of that
        // buffer (slice s-1) all finished before this iteration's barrier.
        if (doA) {
            uint32_t* d = As + ((s + 2) % 3) * AS_B32 + ar * AS_STR + af * 2;
            d[0] = pack_bf16(av.x, av.y);
            d[1] = pack_bf16(av.z, av.w);
        }
    }

    // Fused epilogue: score[row] = sum_h tanh(v+c[h])*W4[h] + b4
    #pragma unroll
    for (int ms = 0; ms < 4; ms++) {
        const int r0 = wm * 64 + ms * 16 + gq;
        const int r1 = r0 + 8;
        float sA = 0.0f, sB = 0.0f;
        #pragma unroll
        for (int ns = 0; ns < 4; ns++) {
            const int n0 = wn * 32 + ns * 8 + 2 * tq;
            const float w0 = w4s[n0], w1 = w4s[n0 + 1];
            const float c0 = cs[n0],  c1 = cs[n0 + 1];
            sA += tanh_fast(acc[ms][ns][0] + c0) * w0
                + tanh_fast(acc[ms][ns][1] + c1) * w1;
            sB += tanh_fast(acc[ms][ns][2] + c0) * w0
                + tanh_fast(acc[ms][ns][3] + c1) * w1;
        }
        sA += __shfl_xor_sync(0xffffffffu, sA, 1);
        sA += __shfl_xor_sync(0xffffffffu, sA, 2);
        sB += __shfl_xor_sync(0xffffffffu, sB, 1);
        sB += __shfl_xor_sync(0xffffffffu, sB, 2);
        if (tq == 0) {
            spart[r0][wn] = sA;
            spart[r1][wn] = sB;
        }
    }
    __syncthreads();
    if (tid < TILE_M) {
        float s = b4[0];
        #pragma unroll
        for (int w = 0; w < 8; w++) s += spart[tid][w];
        g_scores[b * D_SZ + dt * TILE_M + tid] = s;
    }
}

// ---------------------------------------------------------------------------
// Kernel 2: softmax (inline, per-block redundant max/sum) + weighted partial
// sums. grid = (16, B), block = 512. Block (c,b) handles rows c*128..+128.
// ---------------------------------------------------------------------------
__global__ void __launch_bounds__(512)
wsum_kernel(const float* __restrict__ Q) {
    const int b = blockIdx.y;
    const int c = blockIdx.x;
    const int t = threadIdx.x;
    const int lane = t & 31;
    const int wid = t >> 5;
    __shared__ float red[16];
    __shared__ float s_m, s_l;
    __shared__ float ws[128];
    __shared__ float red2[8][256];

    const float* sc = g_scores + b * D_SZ;

    // Block max over all 2048 scores
    float v0 = sc[t], v1 = sc[t + 512], v2 = sc[t + 1024], v3 = sc[t + 1536];
    float m = fmaxf(fmaxf(v0, v1), fmaxf(v2, v3));
    #pragma unroll
    for (int o = 16; o > 0; o >>= 1) m = fmaxf(m, __shfl_xor_sync(~0u, m, o));
    if (lane == 0) red[wid] = m;
    __syncthreads();
    if (t < 32) {
        float mm = (lane < 16) ? red[lane] : -1e30f;
        #pragma unroll
        for (int o = 8; o > 0; o >>= 1) mm = fmaxf(mm, __shfl_xor_sync(~0u, mm, o));
        if (lane == 0) s_m = mm;
    }
    __syncthreads();
    m = s_m;

    // Block sum of exp
    float l = expf(v0 - m) + expf(v1 - m) + expf(v2 - m) + expf(v3 - m);
    #pragma unroll
    for (int o = 16; o > 0; o >>= 1) l += __shfl_xor_sync(~0u, l, o);
    if (lane == 0) red[wid] = l;
    __syncthreads();
    if (t < 32) {
        float ll = (lane < 16) ? red[lane] : 0.0f;
        #pragma unroll
        for (int o = 8; o > 0; o >>= 1) ll += __shfl_xor_sync(~0u, ll, o);
        if (lane == 0) s_l = ll;
    }
    __syncthreads();
    const float invl = 1.0f / s_l;

    // Weights for this block's 128 rows
    if (t < 128) ws[t] = expf(sc[c * 128 + t] - m) * invl;
    __syncthreads();

    // Weighted sum: sd = t>>6 (8 groups x 16 rows), h4 = t&63
    const int h4 = t & 63;
    const int sd = t >> 6;
    const float4* q = reinterpret_cast<const float4*>(
        Q + ((size_t)b * D_SZ + (size_t)c * 128 + (size_t)sd * 16) * H_SZ);
    const float* w = ws + sd * 16;
    float4 acc = make_float4(0.f, 0.f, 0.f, 0.f);
    #pragma unroll
    for (int i = 0; i < 16; i++) {
        float4 v = q[i * 64 + h4];
        float wv = w[i];
        acc.x = fmaf(wv, v.x, acc.x);
        acc.y = fmaf(wv, v.y, acc.y);
        acc.z = fmaf(wv, v.z, acc.z);
        acc.w = fmaf(wv, v.w, acc.w);
    }
    red2[sd][h4 * 4 + 0] = acc.x;
    red2[sd][h4 * 4 + 1] = acc.y;
    red2[sd][h4 * 4 + 2] = acc.z;
    red2[sd][h4 * 4 + 3] = acc.w;
    __syncthreads();
    if (t < 256) {
        float s = 0.0f;
        #pragma unroll
        for (int g = 0; g < 8; g++) s += red2[g][t];
        g_partial[((size_t)b * 16 + c) * H_SZ + t] = s;
    }
}

// ---------------------------------------------------------------------------
// Kernel 3: reduce 16 partials -> out (B,1,H). grid = B_SZ, block = 256.
// ---------------------------------------------------------------------------
__global__ void finalize_kernel(float* __restrict__ out) {
    int b = blockIdx.x;
    int h = threadIdx.x;
    float s = 0.0f;
    #pragma unroll
    for (int p = 0; p < 16; p++)
        s += g_partial[((size_t)b * 16 + p) * H_SZ + h];
    out[b * H_SZ + h] = s;
}

// ---------------------------------------------------------------------------
// Launch. Inputs: 0 context | 1 question | 2 hidden | 3 W1 | 4 W2 | 5 b2
//                 6 W3 | 7 W4 | 8 b4
// ---------------------------------------------------------------------------
extern "C" void kernel_launch(void* const* d_in, const int* in_sizes, int n_in,
                              void* d_out, int out_size) {
    const float* ctx = (const float*)d_in[0];
    const float* qn  = (const float*)d_in[1];
    const float* hid = (const float*)d_in[2];
    const float* W1  = (const float*)d_in[3];
    const float* W2  = (const float*)d_in[4];
    const float* b2  = (const float*)d_in[5];
    const float* W3  = (const float*)d_in[6];
    const float* W4  = (const float*)d_in[7];
    const float* b4  = (const float*)d_in[8];
    float* out = (float*)d_out;

    cudaFuncSetAttribute(gemm_score_bf16,
                         cudaFuncAttributeMaxDynamicSharedMemorySize, DYN_SMEM);

    prep_kernel<<<192, 256>>>(W1, ctx, hid, W2, b2, W3);
    gemm_score_bf16<<<dim3(NDT, B_SZ), 512, DYN_SMEM>>>(qn, W4, b4);
    wsum_kernel<<<dim3(16, B_SZ), 512>>>(qn);
    finalize_kernel<<<B_SZ, 256>>>(out);
}

// round 12
// speedup vs baseline: 1.1883x; 1.1883x over previous
#include <cuda_runtime.h>
#include <cuda_bf16.h>
#include <math.h>
#include <stdint.h>

// Problem constants
#define B_SZ 64
#define D_SZ 2048
#define H_SZ 256

// GEMM tiling: CTA = 128 M x 256 N x 256 K, bf16 fully resident in smem.
#define TILE_M 128
#define NDT    (D_SZ / TILE_M)       // 16
#define KP     (H_SZ / 2)            // 128 bf16x2 pairs per row
#define ROWP   132                   // padded row stride in b32 (128 + 4)
#define A_B32  (TILE_M * ROWP)       // 16896
#define B_B32  (H_SZ * ROWP)        // 33792
#define DYN_SMEM ((A_B32 + B_B32) * 4)   // 202752 bytes

// Scratch (__device__ globals: allocation-free rule)
__device__ float    g_scores [B_SZ * D_SZ];
__device__ float    g_bias   [B_SZ * H_SZ];
__device__ float    g_partial[B_SZ * 16 * H_SZ];
__device__ uint32_t g_w1bf   [H_SZ * H_SZ / 2];   // W1 as bf16x2 pairs

// ---------------- helpers ----------------
__device__ __forceinline__ uint32_t smem_u32(const void* p) {
    uint32_t a;
    asm("{ .reg .u64 t; cvta.to.shared.u64 t, %1; cvt.u32.u64 %0, t; }" : "=r"(a) : "l"(p));
    return a;
}
__device__ __forceinline__ float tanh_fast(float x) {
    float y;
    asm("tanh.approx.f32 %0, %1;" : "=f"(y) : "f"(x));
    return y;
}
__device__ __forceinline__ uint32_t pack_bf16(float lo, float hi) {
    uint32_t r;
    asm("cvt.rn.bf16x2.f32 %0, %1, %2;" : "=r"(r) : "f"(hi), "f"(lo));
    return r;
}
__device__ __forceinline__ void cp16(uint32_t dst, const void* src) {
    asm volatile("cp.async.cg.shared.global [%0], [%1], 16;" :: "r"(dst), "l"(src));
}
__device__ __forceinline__ void mma_bf16(float* d, const uint32_t* a, const uint32_t* b) {
    asm volatile(
        "mma.sync.aligned.m16n8k16.row.col.f32.bf16.bf16.f32 "
        "{%0,%1,%2,%3}, {%4,%5,%6,%7}, {%8,%9}, {%0,%1,%2,%3};"
        : "+f"(d[0]), "+f"(d[1]), "+f"(d[2]), "+f"(d[3])
        : "r"(a[0]), "r"(a[1]), "r"(a[2]), "r"(a[3]), "r"(b[0]), "r"(b[1]));
}

// ---------------------------------------------------------------------------
// Kernel 0: fused prep. Blocks 0..127: W1 fp32 -> bf16x2. Blocks 128..191:
// bias c[b][h] = W2@ctx + b2 + W3@hid.  grid = 192, block = 256.
// ---------------------------------------------------------------------------
__global__ void prep_kernel(const float* __restrict__ W1,
                            const float* __restrict__ ctx,
                            const float* __restrict__ hid,
                            const float* __restrict__ W2,
                            const float* __restrict__ b2,
                            const float* __restrict__ W3) {
    if (blockIdx.x < 128) {
        int i = blockIdx.x * 256 + threadIdx.x;
        float2 v = reinterpret_cast<const float2*>(W1)[i];
        g_w1bf[i] = pack_bf16(v.x, v.y);
        return;
    }
    int b = blockIdx.x - 128;
    int h = threadIdx.x;
    __shared__ float cs[H_SZ];
    __shared__ float hs[H_SZ];
    cs[h] = ctx[b * H_SZ + h];
    hs[h] = hid[b * H_SZ + h];
    __syncthreads();

    const float4* w2r = reinterpret_cast<const float4*>(W2 + (size_t)h * H_SZ);
    const float4* w3r = reinterpret_cast<const float4*>(W3 + (size_t)h * H_SZ);
    float acc = b2[h];
    #pragma unroll 8
    for (int k4 = 0; k4 < H_SZ / 4; k4++) {
        float4 a = w2r[k4], c = w3r[k4];
        int k = k4 * 4;
        acc += cs[k]*a.x + cs[k+1]*a.y + cs[k+2]*a.z + cs[k+3]*a.w;
        acc += hs[k]*c.x + hs[k+1]*c.y + hs[k+2]*c.z + hs[k+3]*c.w;
    }
    g_bias[b * H_SZ + h] = acc;
}

// ---------------------------------------------------------------------------
// Kernel 1: bf16 mma GEMM (Q @ W1^T) fused with tanh(.+c)·W4 -> scores.
// R4 design (measured best): fully-resident tiles, ONE sync after load,
// barrier-free 16-k-step mainloop. 512 threads, 16 warps (wm = wid>>3,
// wn = wid&7; warp tile 64x32). Stride 132 b32 -> fragment LDS
// bank-conflict-free.
// ---------------------------------------------------------------------------
__global__ void __launch_bounds__(512, 1)
gemm_score_bf16(const float* __restrict__ Q,
                const float* __restrict__ W4,
                const float* __restrict__ b4) {
    extern __shared__ uint32_t sm[];
    uint32_t* As = sm;                 // [128][132] bf16x2
    uint32_t* Bs = sm + A_B32;         // [256][132] bf16x2
    __shared__ float cs[H_SZ];
    __shared__ float w4s[H_SZ];
    __shared__ float spart[TILE_M][8];

    const int b    = blockIdx.y;
    const int dt   = blockIdx.x;
    const int tid  = threadIdx.x;
    const int wid  = tid >> 5;
    const int lane = tid & 31;
    const int wm   = wid >> 3;         // 0..1
    const int wn   = wid & 7;          // 0..7
    const int gq   = lane >> 2;        // 0..7
    const int tq   = lane & 3;         // 0..3

    if (tid < H_SZ) {
        cs[tid]  = g_bias[b * H_SZ + tid];
        w4s[tid] = W4[tid];
    }

    // --- Load B (W1 bf16) via cp.async: 256 rows x 512B, 16 chunks/thread ---
    {
        const uint32_t bbase = smem_u32(Bs);
        const char* src = reinterpret_cast<const char*>(g_w1bf);
        #pragma unroll
        for (int j = 0; j < 16; j++) {
            int idx = j * 512 + tid;
            int n = idx >> 5, c = idx & 31;
            cp16(bbase + (uint32_t)(n * ROWP + c * 4) * 4, src + n * 512 + c * 16);
        }
        asm volatile("cp.async.commit_group;" ::: "memory");
    }

    // --- Load + convert A (question tile): 128 rows x 128 pairs ---
    {
        const float2* qg = reinterpret_cast<const float2*>(
            Q + ((size_t)b * D_SZ + (size_t)dt * TILE_M) * H_SZ);
        #pragma unroll
        for (int j = 0; j < 32; j++) {
            int idx = j * 512 + tid;
            int m = idx >> 7, p = idx & 127;
            float2 v = qg[m * KP + p];
            As[m * ROWP + p] = pack_bf16(v.x, v.y);
        }
    }
    asm volatile("cp.async.wait_group 0;" ::: "memory");
    __syncthreads();

    // --- Mainloop: 16 k-steps of 16, no barriers ---
    float acc[4][4][4];
    #pragma unroll
    for (int i = 0; i < 4; i++)
        #pragma unroll
        for (int j = 0; j < 4; j++)
            #pragma unroll
            for (int r = 0; r < 4; r++) acc[i][j][r] = 0.0f;

    const uint32_t* aRow[4];
    const uint32_t* bRow[4];
    #pragma unroll
    for (int ms = 0; ms < 4; ms++)
        aRow[ms] = As + (wm * 64 + ms * 16 + gq) * ROWP + tq;
    #pragma unroll
    for (int ns = 0; ns < 4; ns++)
        bRow[ns] = Bs + (wn * 32 + ns * 8 + gq) * ROWP + tq;

    #pragma unroll
    for (int k16 = 0; k16 < 16; k16++) {
        const int kb = k16 * 8;
        uint32_t a[4][4], bb[4][2];
        #pragma unroll
        for (int ms = 0; ms < 4; ms++) {
            a[ms][0] = aRow[ms][kb];
            a[ms][1] = aRow[ms][8 * ROWP + kb];
            a[ms][2] = aRow[ms][kb + 4];
            a[ms][3] = aRow[ms][8 * ROWP + kb + 4];
        }
        #pragma unroll
        for (int ns = 0; ns < 4; ns++) {
            bb[ns][0] = bRow[ns][kb];
            bb[ns][1] = bRow[ns][kb + 4];
        }
        #pragma unroll
        for (int ms = 0; ms < 4; ms++)
            #pragma unroll
            for (int ns = 0; ns < 4; ns++)
                mma_bf16(acc[ms][ns], a[ms], bb[ns]);
    }

    // --- Fused epilogue: score[row] = sum_h tanh(v+c[h])*W4[h] ---
    #pragma unroll
    for (int ms = 0; ms < 4; ms++) {
        const int r0 = wm * 64 + ms * 16 + gq;
        const int r1 = r0 + 8;
        float sA = 0.0f, sB = 0.0f;
        #pragma unroll
        for (int ns = 0; ns < 4; ns++) {
            const int n0 = wn * 32 + ns * 8 + 2 * tq;
            const float w0 = w4s[n0], w1 = w4s[n0 + 1];
            const float c0 = cs[n0],  c1 = cs[n0 + 1];
            sA += tanh_fast(acc[ms][ns][0] + c0) * w0
                + tanh_fast(acc[ms][ns][1] + c1) * w1;
            sB += tanh_fast(acc[ms][ns][2] + c0) * w0
                + tanh_fast(acc[ms][ns][3] + c1) * w1;
        }
        sA += __shfl_xor_sync(0xffffffffu, sA, 1);
        sA += __shfl_xor_sync(0xffffffffu, sA, 2);
        sB += __shfl_xor_sync(0xffffffffu, sB, 1);
        sB += __shfl_xor_sync(0xffffffffu, sB, 2);
        if (tq == 0) {
            spart[r0][wn] = sA;
            spart[r1][wn] = sB;
        }
    }
    __syncthreads();
    if (tid < TILE_M) {
        float s = b4[0];
        #pragma unroll
        for (int w = 0; w < 8; w++) s += spart[tid][w];
        g_scores[b * D_SZ + dt * TILE_M + tid] = s;
    }
}

// ---------------------------------------------------------------------------
// Kernel 2: softmax (inline, per-block redundant max/sum) + weighted partial
// sums. grid = (16, B), block = 512. Block (c,b) handles rows c*128..+128.
// ---------------------------------------------------------------------------
__global__ void __launch_bounds__(512)
wsum_kernel(const float* __restrict__ Q) {
    const int b = blockIdx.y;
    const int c = blockIdx.x;
    const int t = threadIdx.x;
    const int lane = t & 31;
    const int wid = t >> 5;
    __shared__ float red[16];
    __shared__ float s_m, s_l;
    __shared__ float ws[128];
    __shared__ float red2[8][256];

    const float* sc = g_scores + b * D_SZ;

    // Block max over all 2048 scores
    float v0 = sc[t], v1 = sc[t + 512], v2 = sc[t + 1024], v3 = sc[t + 1536];
    float m = fmaxf(fmaxf(v0, v1), fmaxf(v2, v3));
    #pragma unroll
    for (int o = 16; o > 0; o >>= 1) m = fmaxf(m, __shfl_xor_sync(~0u, m, o));
    if (lane == 0) red[wid] = m;
    __syncthreads();
    if (t < 32) {
        float mm = (lane < 16) ? red[lane] : -1e30f;
        #pragma unroll
        for (int o = 8; o > 0; o >>= 1) mm = fmaxf(mm, __shfl_xor_sync(~0u, mm, o));
        if (lane == 0) s_m = mm;
    }
    __syncthreads();
    m = s_m;

    // Block sum of exp
    float l = expf(v0 - m) + expf(v1 - m) + expf(v2 - m) + expf(v3 - m);
    #pragma unroll
    for (int o = 16; o > 0; o >>= 1) l += __shfl_xor_sync(~0u, l, o);
    if (lane == 0) red[wid] = l;
    __syncthreads();
    if (t < 32) {
        float ll = (lane < 16) ? red[lane] : 0.0f;
        #pragma unroll
        for (int o = 8; o > 0; o >>= 1) ll += __shfl_xor_sync(~0u, ll, o);
        if (lane == 0) s_l = ll;
    }
    __syncthreads();
    const float invl = 1.0f / s_l;

    // Weights for this block's 128 rows
    if (t < 128) ws[t] = expf(sc[c * 128 + t] - m) * invl;
    __syncthreads();

    // Weighted sum: sd = t>>6 (8 groups x 16 rows), h4 = t&63
    const int h4 = t & 63;
    const int sd = t >> 6;
    const float4* q = reinterpret_cast<const float4*>(
        Q + ((size_t)b * D_SZ + (size_t)c * 128 + (size_t)sd * 16) * H_SZ);
    const float* w = ws + sd * 16;
    float4 acc = make_float4(0.f, 0.f, 0.f, 0.f);
    #pragma unroll
    for (int i = 0; i < 16; i++) {
        float4 v = q[i * 64 + h4];
        float wv = w[i];
        acc.x = fmaf(wv, v.x, acc.x);
        acc.y = fmaf(wv, v.y, acc.y);
        acc.z = fmaf(wv, v.z, acc.z);
        acc.w = fmaf(wv, v.w, acc.w);
    }
    red2[sd][h4 * 4 + 0] = acc.x;
    red2[sd][h4 * 4 + 1] = acc.y;
    red2[sd][h4 * 4 + 2] = acc.z;
    red2[sd][h4 * 4 + 3] = acc.w;
    __syncthreads();
    if (t < 256) {
        float s = 0.0f;
        #pragma unroll
        for (int g = 0; g < 8; g++) s += red2[g][t];
        g_partial[((size_t)b * 16 + c) * H_SZ + t] = s;
    }
}

// ---------------------------------------------------------------------------
// Kernel 3: reduce 16 partials -> out (B,1,H). grid = B_SZ, block = 256.
// ---------------------------------------------------------------------------
__global__ void finalize_kernel(float* __restrict__ out) {
    int b = blockIdx.x;
    int h = threadIdx.x;
    float s = 0.0f;
    #pragma unroll
    for (int p = 0; p < 16; p++)
        s += g_partial[((size_t)b * 16 + p) * H_SZ + h];
    out[b * H_SZ + h] = s;
}

// ---------------------------------------------------------------------------
// Launch. Inputs: 0 context | 1 question | 2 hidden | 3 W1 | 4 W2 | 5 b2
//                 6 W3 | 7 W4 | 8 b4
// ---------------------------------------------------------------------------
extern "C" void kernel_launch(void* const* d_in, const int* in_sizes, int n_in,
                              void* d_out, int out_size) {
    const float* ctx = (const float*)d_in[0];
    const float* qn  = (const float*)d_in[1];
    const float* hid = (const float*)d_in[2];
    const float* W1  = (const float*)d_in[3];
    const float* W2  = (const float*)d_in[4];
    const float* b2  = (const float*)d_in[5];
    const float* W3  = (const float*)d_in[6];
    const float* W4  = (const float*)d_in[7];
    const float* b4  = (const float*)d_in[8];
    float* out = (float*)d_out;

    cudaFuncSetAttribute(gemm_score_bf16,
                         cudaFuncAttributeMaxDynamicSharedMemorySize, DYN_SMEM);

    prep_kernel<<<192, 256>>>(W1, ctx, hid, W2, b2, W3);
    gemm_score_bf16<<<dim3(NDT, B_SZ), 512, DYN_SMEM>>>(qn, W4, b4);
    wsum_kernel<<<dim3(16, B_SZ), 512>>>(qn);
    finalize_kernel<<<B_SZ, 256>>>(out);
}

// round 13
// speedup vs baseline: 1.2389x; 1.0425x over previous
#include <cuda_runtime.h>
#include <cuda_bf16.h>
#include <math.h>
#include <stdint.h>

// Problem constants
#define B_SZ 64
#define D_SZ 2048
#define H_SZ 256
#define NCHUNK 8

// GEMM tiling: CTA = 128 M x 256 N x 256 K, bf16 fully resident in smem.
#define TILE_M 128
#define NDT    (D_SZ / TILE_M)       // 16
#define KP     (H_SZ / 2)            // 128 bf16x2 pairs per row
#define ROWP   132                   // padded row stride in b32 (128 + 4)
#define A_B32  (TILE_M * ROWP)       // 16896
#define B_B32  (H_SZ * ROWP)         // 33792
#define DYN_SMEM ((A_B32 + B_B32) * 4)   // 202752 bytes

// Scratch (__device__ globals: allocation-free rule)
__device__ float    g_scores [B_SZ * D_SZ];
__device__ float    g_bias   [B_SZ * H_SZ];
__device__ float    g_partial[B_SZ * 64 * H_SZ];
__device__ uint32_t g_w1bf   [H_SZ * H_SZ / 2];   // W1 as bf16x2 pairs

// ---------------- helpers ----------------
__device__ __forceinline__ uint32_t smem_u32(const void* p) {
    uint32_t a;
    asm("{ .reg .u64 t; cvta.to.shared.u64 t, %1; cvt.u32.u64 %0, t; }" : "=r"(a) : "l"(p));
    return a;
}
__device__ __forceinline__ float tanh_fast(float x) {
    float y;
    asm("tanh.approx.f32 %0, %1;" : "=f"(y) : "f"(x));
    return y;
}
__device__ __forceinline__ uint32_t pack_bf16(float lo, float hi) {
    uint32_t r;
    asm("cvt.rn.bf16x2.f32 %0, %1, %2;" : "=r"(r) : "f"(hi), "f"(lo));
    return r;
}
__device__ __forceinline__ void cp16(uint32_t dst, const void* src) {
    asm volatile("cp.async.cg.shared.global [%0], [%1], 16;" :: "r"(dst), "l"(src));
}
__device__ __forceinline__ void mma_bf16(float* d, const uint32_t* a, const uint32_t* b) {
    asm volatile(
        "mma.sync.aligned.m16n8k16.row.col.f32.bf16.bf16.f32 "
        "{%0,%1,%2,%3}, {%4,%5,%6,%7}, {%8,%9}, {%0,%1,%2,%3};"
        : "+f"(d[0]), "+f"(d[1]), "+f"(d[2]), "+f"(d[3])
        : "r"(a[0]), "r"(a[1]), "r"(a[2]), "r"(a[3]), "r"(b[0]), "r"(b[1]));
}

// ---------------------------------------------------------------------------
// Kernel 0: fused prep. Blocks 0..127: W1 fp32 -> bf16x2. Blocks 128..191:
// bias c[b][h] = W2@ctx + b2 + W3@hid.  grid = 192, block = 256.
// ---------------------------------------------------------------------------
__global__ void prep_kernel(const float* __restrict__ W1,
                            const float* __restrict__ ctx,
                            const float* __restrict__ hid,
                            const float* __restrict__ W2,
                            const float* __restrict__ b2,
                            const float* __restrict__ W3) {
    if (blockIdx.x < 128) {
        int i = blockIdx.x * 256 + threadIdx.x;
        float2 v = reinterpret_cast<const float2*>(W1)[i];
        g_w1bf[i] = pack_bf16(v.x, v.y);
        return;
    }
    int b = blockIdx.x - 128;
    int h = threadIdx.x;
    __shared__ float cs[H_SZ];
    __shared__ float hs[H_SZ];
    cs[h] = ctx[b * H_SZ + h];
    hs[h] = hid[b * H_SZ + h];
    __syncthreads();

    const float4* w2r = reinterpret_cast<const float4*>(W2 + (size_t)h * H_SZ);
    const float4* w3r = reinterpret_cast<const float4*>(W3 + (size_t)h * H_SZ);
    float acc = b2[h];
    #pragma unroll 8
    for (int k4 = 0; k4 < H_SZ / 4; k4++) {
        float4 a = w2r[k4], c = w3r[k4];
        int k = k4 * 4;
        acc += cs[k]*a.x + cs[k+1]*a.y + cs[k+2]*a.z + cs[k+3]*a.w;
        acc += hs[k]*c.x + hs[k+1]*c.y + hs[k+2]*c.z + hs[k+3]*c.w;
    }
    g_bias[b * H_SZ + h] = acc;
}

// ---------------------------------------------------------------------------
// Kernel 1: bf16 mma GEMM (Q @ W1^T) fused with tanh(.+c)·W4 -> scores.
// R4 design (measured best): fully-resident tiles, ONE sync after load,
// barrier-free 16-k-step mainloop. 512 threads, 16 warps (wm = wid>>3,
// wn = wid&7; warp tile 64x32). Stride 132 b32 -> fragment LDS
// bank-conflict-free. A-load uses float4 LDGs (16 per thread).
// ---------------------------------------------------------------------------
__global__ void __launch_bounds__(512, 1)
gemm_score_bf16(const float* __restrict__ Q,
                const float* __restrict__ W4,
                const float* __restrict__ b4) {
    extern __shared__ uint32_t sm[];
    uint32_t* As = sm;                 // [128][132] bf16x2
    uint32_t* Bs = sm + A_B32;         // [256][132] bf16x2
    __shared__ float cs[H_SZ];
    __shared__ float w4s[H_SZ];
    __shared__ float spart[TILE_M][8];

    const int b    = blockIdx.y;
    const int dt   = blockIdx.x;
    const int tid  = threadIdx.x;
    const int wid  = tid >> 5;
    const int lane = tid & 31;
    const int wm   = wid >> 3;         // 0..1
    const int wn   = wid & 7;          // 0..7
    const int gq   = lane >> 2;        // 0..7
    const int tq   = lane & 3;         // 0..3

    if (tid < H_SZ) {
        cs[tid]  = g_bias[b * H_SZ + tid];
        w4s[tid] = W4[tid];
    }

    // --- Load B (W1 bf16) via cp.async: 256 rows x 512B, 16 chunks/thread ---
    {
        const uint32_t bbase = smem_u32(Bs);
        const char* src = reinterpret_cast<const char*>(g_w1bf);
        #pragma unroll
        for (int j = 0; j < 16; j++) {
            int idx = j * 512 + tid;
            int n = idx >> 5, c = idx & 31;
            cp16(bbase + (uint32_t)(n * ROWP + c * 4) * 4, src + n * 512 + c * 16);
        }
        asm volatile("cp.async.commit_group;" ::: "memory");
    }

    // --- Load + convert A (question tile): 128 rows x 64 float4 ---
    {
        const float4* qg = reinterpret_cast<const float4*>(
            Q + ((size_t)b * D_SZ + (size_t)dt * TILE_M) * H_SZ);
        #pragma unroll
        for (int j = 0; j < 16; j++) {
            int idx = j * 512 + tid;       // float4 index: m = idx>>6, f4 = idx&63
            int m = idx >> 6, f4 = idx & 63;
            float4 v = qg[idx];
            uint32_t* d = As + m * ROWP + f4 * 2;
            d[0] = pack_bf16(v.x, v.y);
            d[1] = pack_bf16(v.z, v.w);
        }
    }
    asm volatile("cp.async.wait_group 0;" ::: "memory");
    __syncthreads();

    // --- Mainloop: 16 k-steps of 16, no barriers ---
    float acc[4][4][4];
    #pragma unroll
    for (int i = 0; i < 4; i++)
        #pragma unroll
        for (int j = 0; j < 4; j++)
            #pragma unroll
            for (int r = 0; r < 4; r++) acc[i][j][r] = 0.0f;

    const uint32_t* aRow[4];
    const uint32_t* bRow[4];
    #pragma unroll
    for (int ms = 0; ms < 4; ms++)
        aRow[ms] = As + (wm * 64 + ms * 16 + gq) * ROWP + tq;
    #pragma unroll
    for (int ns = 0; ns < 4; ns++)
        bRow[ns] = Bs + (wn * 32 + ns * 8 + gq) * ROWP + tq;

    #pragma unroll
    for (int k16 = 0; k16 < 16; k16++) {
        const int kb = k16 * 8;
        uint32_t a[4][4], bb[4][2];
        #pragma unroll
        for (int ms = 0; ms < 4; ms++) {
            a[ms][0] = aRow[ms][kb];
            a[ms][1] = aRow[ms][8 * ROWP + kb];
            a[ms][2] = aRow[ms][kb + 4];
            a[ms][3] = aRow[ms][8 * ROWP + kb + 4];
        }
        #pragma unroll
        for (int ns = 0; ns < 4; ns++) {
            bb[ns][0] = bRow[ns][kb];
            bb[ns][1] = bRow[ns][kb + 4];
        }
        #pragma unroll
        for (int ms = 0; ms < 4; ms++)
            #pragma unroll
            for (int ns = 0; ns < 4; ns++)
                mma_bf16(acc[ms][ns], a[ms], bb[ns]);
    }

    // --- Fused epilogue: score[row] = sum_h tanh(v+c[h])*W4[h] ---
    #pragma unroll
    for (int ms = 0; ms < 4; ms++) {
        const int r0 = wm * 64 + ms * 16 + gq;
        const int r1 = r0 + 8;
        float sA = 0.0f, sB = 0.0f;
        #pragma unroll
        for (int ns = 0; ns < 4; ns++) {
            const int n0 = wn * 32 + ns * 8 + 2 * tq;
            const float w0 = w4s[n0], w1 = w4s[n0 + 1];
            const float c0 = cs[n0],  c1 = cs[n0 + 1];
            sA += tanh_fast(acc[ms][ns][0] + c0) * w0
                + tanh_fast(acc[ms][ns][1] + c1) * w1;
            sB += tanh_fast(acc[ms][ns][2] + c0) * w0
                + tanh_fast(acc[ms][ns][3] + c1) * w1;
        }
        sA += __shfl_xor_sync(0xffffffffu, sA, 1);
        sA += __shfl_xor_sync(0xffffffffu, sA, 2);
        sB += __shfl_xor_sync(0xffffffffu, sB, 1);
        sB += __shfl_xor_sync(0xffffffffu, sB, 2);
        if (tq == 0) {
            spart[r0][wn] = sA;
            spart[r1][wn] = sB;
        }
    }
    __syncthreads();
    if (tid < TILE_M) {
        float s = b4[0];
        #pragma unroll
        for (int w = 0; w < 8; w++) s += spart[tid][w];
        g_scores[b * D_SZ + dt * TILE_M + tid] = s;
    }
}

// ---------------------------------------------------------------------------
// Kernel 2: softmax over D per batch. grid = B_SZ, block = 256. (R4 exact)
// ---------------------------------------------------------------------------
__global__ void softmax_kernel() {
    int b = blockIdx.x;
    int tid = threadIdx.x;
    __shared__ float red[256];

    float v[NCHUNK];
    float m = -1e30f;
    #pragma unroll
    for (int i = 0; i < NCHUNK; i++) {
        v[i] = g_scores[b * D_SZ + i * 256 + tid];
        m = fmaxf(m, v[i]);
    }
    red[tid] = m;
    __syncthreads();
    for (int s = 128; s > 0; s >>= 1) {
        if (tid < s) red[tid] = fmaxf(red[tid], red[tid + s]);
        __syncthreads();
    }
    m = red[0];
    __syncthreads();

    float ssum = 0.0f;
    #pragma unroll
    for (int i = 0; i < NCHUNK; i++) { v[i] = expf(v[i] - m); ssum += v[i]; }
    red[tid] = ssum;
    __syncthreads();
    for (int s = 128; s > 0; s >>= 1) {
        if (tid < s) red[tid] += red[tid + s];
        __syncthreads();
    }
    float inv = 1.0f / red[0];

    #pragma unroll
    for (int i = 0; i < NCHUNK; i++)
        g_scores[b * D_SZ + i * 256 + tid] = v[i] * inv;
}

// ---------------------------------------------------------------------------
// Kernel 3: weighted partial sums, 128-row chunks. grid=(16,B), block=256.
// (R4 exact)
// ---------------------------------------------------------------------------
__global__ void __launch_bounds__(256)
wsum_kernel(const float* __restrict__ Q) {
    int b = blockIdx.y;
    int c = blockIdx.x;       // 0..15
    int t = threadIdx.x;
    int h4 = t & 63;
    int sd = t >> 6;          // 0..3
    __shared__ float ws[128];
    if (t < 128) ws[t] = g_scores[b * D_SZ + c * 128 + t];
    __syncthreads();

    const float4* q = reinterpret_cast<const float4*>(
        Q + ((size_t)b * D_SZ + (size_t)c * 128 + (size_t)sd * 32) * H_SZ);
    const float* w = ws + sd * 32;
    float4 acc = make_float4(0.f, 0.f, 0.f, 0.f);
    #pragma unroll 8
    for (int i = 0; i < 32; i++) {
        float4 v = q[i * 64 + h4];
        float wv = w[i];
        acc.x = fmaf(wv, v.x, acc.x);
        acc.y = fmaf(wv, v.y, acc.y);
        acc.z = fmaf(wv, v.z, acc.z);
        acc.w = fmaf(wv, v.w, acc.w);
    }
    float4* dst = reinterpret_cast<float4*>(
        g_partial + ((size_t)b * 64 + (size_t)c * 4 + sd) * H_SZ);
    dst[h4] = acc;
}

// ---------------------------------------------------------------------------
// Kernel 4: reduce 64 partials -> out (B,1,H). grid = B_SZ, block = 256.
// (R4 exact)
// ---------------------------------------------------------------------------
__global__ void finalize_kernel(float* __restrict__ out) {
    int b = blockIdx.x;
    int h = threadIdx.x;
    float s = 0.0f;
    #pragma unroll
    for (int p = 0; p < 64; p++)
        s += g_partial[((size_t)b * 64 + p) * H_SZ + h];
    out[b * H_SZ + h] = s;
}

// ---------------------------------------------------------------------------
// Launch. Inputs: 0 context | 1 question | 2 hidden | 3 W1 | 4 W2 | 5 b2
//                 6 W3 | 7 W4 | 8 b4
// ---------------------------------------------------------------------------
extern "C" void kernel_launch(void* const* d_in, const int* in_sizes, int n_in,
                              void* d_out, int out_size) {
    const float* ctx = (const float*)d_in[0];
    const float* qn  = (const float*)d_in[1];
    const float* hid = (const float*)d_in[2];
    const float* W1  = (const float*)d_in[3];
    const float* W2  = (const float*)d_in[4];
    const float* b2  = (const float*)d_in[5];
    const float* W3  = (const float*)d_in[6];
    const float* W4  = (const float*)d_in[7];
    const float* b4  = (const float*)d_in[8];
    float* out = (float*)d_out;

    cudaFuncSetAttribute(gemm_score_bf16,
                         cudaFuncAttributeMaxDynamicSharedMemorySize, DYN_SMEM);

    prep_kernel<<<192, 256>>>(W1, ctx, hid, W2, b2, W3);
    gemm_score_bf16<<<dim3(NDT, B_SZ), 512, DYN_SMEM>>>(qn, W4, b4);
    softmax_kernel<<<B_SZ, 256>>>();
    wsum_kernel<<<dim3(16, B_SZ), 256>>>(qn);
    finalize_kernel<<<B_SZ, 256>>>(out);
}

// round 14
// speedup vs baseline: 1.2397x; 1.0007x over previous
#include <cuda_runtime.h>
#include <cuda_bf16.h>
#include <math.h>
#include <stdint.h>

// Problem constants
#define B_SZ 64
#define D_SZ 2048
#define H_SZ 256
#define NCHUNK 8

// GEMM tiling: CTA = 128 M x 256 N x 256 K, bf16 fully resident in smem.
// 256 threads, 8 warps, warp tile 64x64.
#define TILE_M 128
#define NDT    (D_SZ / TILE_M)       // 16
#define ROWP   132                   // padded row stride in b32 (128 + 4)
#define A_B32  (TILE_M * ROWP)       // 16896
#define B_B32  (H_SZ * ROWP)         // 33792
#define DYN_SMEM ((A_B32 + B_B32) * 4)   // 202752 bytes

// Scratch (__device__ globals: allocation-free rule)
__device__ float    g_scores [B_SZ * D_SZ];
__device__ float    g_bias   [B_SZ * H_SZ];
__device__ float    g_partial[B_SZ * 64 * H_SZ];
__device__ uint32_t g_w1bf   [H_SZ * H_SZ / 2];   // W1 as bf16x2 pairs

// ---------------- helpers ----------------
__device__ __forceinline__ uint32_t smem_u32(const void* p) {
    uint32_t a;
    asm("{ .reg .u64 t; cvta.to.shared.u64 t, %1; cvt.u32.u64 %0, t; }" : "=r"(a) : "l"(p));
    return a;
}
__device__ __forceinline__ float tanh_fast(float x) {
    float y;
    asm("tanh.approx.f32 %0, %1;" : "=f"(y) : "f"(x));
    return y;
}
__device__ __forceinline__ uint32_t pack_bf16(float lo, float hi) {
    uint32_t r;
    asm("cvt.rn.bf16x2.f32 %0, %1, %2;" : "=r"(r) : "f"(hi), "f"(lo));
    return r;
}
__device__ __forceinline__ void cp16(uint32_t dst, const void* src) {
    asm volatile("cp.async.cg.shared.global [%0], [%1], 16;" :: "r"(dst), "l"(src));
}
__device__ __forceinline__ void mma_bf16(float* d, const uint32_t* a, const uint32_t* b) {
    asm volatile(
        "mma.sync.aligned.m16n8k16.row.col.f32.bf16.bf16.f32 "
        "{%0,%1,%2,%3}, {%4,%5,%6,%7}, {%8,%9}, {%0,%1,%2,%3};"
        : "+f"(d[0]), "+f"(d[1]), "+f"(d[2]), "+f"(d[3])
        : "r"(a[0]), "r"(a[1]), "r"(a[2]), "r"(a[3]), "r"(b[0]), "r"(b[1]));
}

// ---------------------------------------------------------------------------
// Kernel 0: fused prep. Blocks 0..127: W1 fp32 -> bf16x2. Blocks 128..191:
// bias c[b][h] = W2@ctx + b2 + W3@hid.  grid = 192, block = 256.
// ---------------------------------------------------------------------------
__global__ void prep_kernel(const float* __restrict__ W1,
                            const float* __restrict__ ctx,
                            const float* __restrict__ hid,
                            const float* __restrict__ W2,
                            const float* __restrict__ b2,
                            const float* __restrict__ W3) {
    if (blockIdx.x < 128) {
        int i = blockIdx.x * 256 + threadIdx.x;
        float2 v = reinterpret_cast<const float2*>(W1)[i];
        g_w1bf[i] = pack_bf16(v.x, v.y);
        return;
    }
    int b = blockIdx.x - 128;
    int h = threadIdx.x;
    __shared__ float cs[H_SZ];
    __shared__ float hs[H_SZ];
    cs[h] = ctx[b * H_SZ + h];
    hs[h] = hid[b * H_SZ + h];
    __syncthreads();

    const float4* w2r = reinterpret_cast<const float4*>(W2 + (size_t)h * H_SZ);
    const float4* w3r = reinterpret_cast<const float4*>(W3 + (size_t)h * H_SZ);
    float acc = b2[h];
    #pragma unroll 8
    for (int k4 = 0; k4 < H_SZ / 4; k4++) {
        float4 a = w2r[k4], c = w3r[k4];
        int k = k4 * 4;
        acc += cs[k]*a.x + cs[k+1]*a.y + cs[k+2]*a.z + cs[k+3]*a.w;
        acc += hs[k]*c.x + hs[k+1]*c.y + hs[k+2]*c.z + hs[k+3]*c.w;
    }
    g_bias[b * H_SZ + h] = acc;
}

// ---------------------------------------------------------------------------
// Kernel 1: bf16 mma GEMM (Q @ W1^T) fused with tanh(.+c)·W4 -> scores.
// 256 threads, 8 warps, warp tile 64x64 (wm = wid>>2, wn = wid&3).
// 2-stage K: A half0 loaded up front; A half1 prefetched in 4 register
// groups DURING half0 compute (written to the disjoint half1 smem region,
// so no extra barriers beyond the two stage syncs). B fully cp.async.
// Stride 132 b32 -> all fragment LDS conflict-free.
// ---------------------------------------------------------------------------
__global__ void __launch_bounds__(256, 1)
gemm_score_bf16(const float* __restrict__ Q,
                const float* __restrict__ W4,
                const float* __restrict__ b4) {
    extern __shared__ uint32_t sm[];
    uint32_t* As = sm;                 // [128][132] bf16x2
    uint32_t* Bs = sm + A_B32;         // [256][132] bf16x2
    __shared__ float cs[H_SZ];
    __shared__ float w4s[H_SZ];
    __shared__ float spart[TILE_M][4];

    const int b    = blockIdx.y;
    const int dt   = blockIdx.x;
    const int tid  = threadIdx.x;
    const int wid  = tid >> 5;
    const int lane = tid & 31;
    const int wm   = wid >> 2;         // 0..1
    const int wn   = wid & 3;          // 0..3
    const int gq   = lane >> 2;        // 0..7
    const int tq   = lane & 3;         // 0..3

    cs[tid]  = g_bias[b * H_SZ + tid];
    w4s[tid] = W4[tid];

    // --- B (W1 bf16) via cp.async: 8192 16B chunks, 32 per thread ---
    {
        const uint32_t bbase = smem_u32(Bs);
        const char* src = reinterpret_cast<const char*>(g_w1bf);
        #pragma unroll
        for (int j = 0; j < 32; j++) {
            int idx = j * 256 + tid;
            int n = idx >> 5, c = idx & 31;
            cp16(bbase + (uint32_t)(n * ROWP + c * 4) * 4, src + n * 512 + c * 16);
        }
        asm volatile("cp.async.commit_group;" ::: "memory");
    }

    const float4* qg = reinterpret_cast<const float4*>(
        Q + ((size_t)b * D_SZ + (size_t)dt * TILE_M) * H_SZ);

    // --- A half0 (cols 0..127 fp32): 4096 f4, 16 per thread ---
    #pragma unroll
    for (int j = 0; j < 16; j++) {
        int idx = j * 256 + tid;
        int row = idx >> 5, c = idx & 31;          // c: f4 within half (0..31)
        float4 v = qg[row * 64 + c];
        uint32_t* d = As + row * ROWP + c * 2;
        d[0] = pack_bf16(v.x, v.y);
        d[1] = pack_bf16(v.z, v.w);
    }
    asm volatile("cp.async.wait_group 0;" ::: "memory");
    __syncthreads();                                // stage barrier 1

    float acc[4][8][4];
    #pragma unroll
    for (int i = 0; i < 4; i++)
        #pragma unroll
        for (int j = 0; j < 8; j++)
            #pragma unroll
            for (int r = 0; r < 4; r++) acc[i][j][r] = 0.0f;

    int aOff[4], bOff[8];
    #pragma unroll
    for (int ms = 0; ms < 4; ms++)
        aOff[ms] = (wm * 64 + ms * 16 + gq) * ROWP + tq;
    #pragma unroll
    for (int ns = 0; ns < 8; ns++)
        bOff[ns] = (wn * 64 + ns * 8 + gq) * ROWP + tq;

    // one k16 step
    #define K_STEP(k16) do {                                            \
        const int kb = (k16) * 8;                                       \
        uint32_t a[4][4], bb[8][2];                                     \
        _Pragma("unroll")                                               \
        for (int ms = 0; ms < 4; ms++) {                                \
            a[ms][0] = As[aOff[ms] + kb];                               \
            a[ms][1] = As[aOff[ms] + 8 * ROWP + kb];                    \
            a[ms][2] = As[aOff[ms] + kb + 4];                           \
            a[ms][3] = As[aOff[ms] + 8 * ROWP + kb + 4];                \
        }                                                               \
        _Pragma("unroll")                                               \
        for (int ns = 0; ns < 8; ns++) {                                \
            bb[ns][0] = Bs[bOff[ns] + kb];                              \
            bb[ns][1] = Bs[bOff[ns] + kb + 4];                          \
        }                                                               \
        _Pragma("unroll")                                               \
        for (int ms = 0; ms < 4; ms++)                                  \
            _Pragma("unroll")                                           \
            for (int ns = 0; ns < 8; ns++)                              \
                mma_bf16(acc[ms][ns], a[ms], bb[ns]);                   \
    } while (0)

    // --- half0 compute (k-steps 0..7), interleaved with A half1 prefetch ---
    #pragma unroll
    for (int g = 0; g < 4; g++) {
        // prefetch group g of half1: 4 f4/thread (issued before 2 k-steps)
        float4 pf[4];
        int rowp[4], cp_[4];
        #pragma unroll
        for (int u = 0; u < 4; u++) {
            int idx = (g * 4 + u) * 256 + tid;
            rowp[u] = idx >> 5;
            cp_[u]  = idx & 31;
            pf[u] = qg[rowp[u] * 64 + 32 + cp_[u]];   // half1 cols
        }
        K_STEP(2 * g);
        K_STEP(2 * g + 1);
        // store prefetched group into half1 region (disjoint from half0 reads)
        #pragma unroll
        for (int u = 0; u < 4; u++) {
            uint32_t* d = As + rowp[u] * ROWP + 64 + cp_[u] * 2;
            d[0] = pack_bf16(pf[u].x, pf[u].y);
            d[1] = pack_bf16(pf[u].z, pf[u].w);
        }
    }
    __syncthreads();                                // stage barrier 2

    // --- half1 compute (k-steps 8..15) ---
    #pragma unroll
    for (int k16 = 8; k16 < 16; k16++)
        K_STEP(k16);
    #undef K_STEP

    // --- Fused epilogue: score[row] = sum_h tanh(v+c[h])*W4[h] ---
    #pragma unroll
    for (int ms = 0; ms < 4; ms++) {
        const int r0 = wm * 64 + ms * 16 + gq;
        const int r1 = r0 + 8;
        float sA = 0.0f, sB = 0.0f;
        #pragma unroll
        for (int ns = 0; ns < 8; ns++) {
            const int n0 = wn * 64 + ns * 8 + 2 * tq;
            const float w0 = w4s[n0], w1 = w4s[n0 + 1];
            const float c0 = cs[n0],  c1 = cs[n0 + 1];
            sA += tanh_fast(acc[ms][ns][0] + c0) * w0
                + tanh_fast(acc[ms][ns][1] + c1) * w1;
            sB += tanh_fast(acc[ms][ns][2] + c0) * w0
                + tanh_fast(acc[ms][ns][3] + c1) * w1;
        }
        sA += __shfl_xor_sync(0xffffffffu, sA, 1);
        sA += __shfl_xor_sync(0xffffffffu, sA, 2);
        sB += __shfl_xor_sync(0xffffffffu, sB, 1);
        sB += __shfl_xor_sync(0xffffffffu, sB, 2);
        if (tq == 0) {
            spart[r0][wn] = sA;
            spart[r1][wn] = sB;
        }
    }
    __syncthreads();
    if (tid < TILE_M) {
        float s = b4[0] + spart[tid][0] + spart[tid][1]
                        + spart[tid][2] + spart[tid][3];
        g_scores[b * D_SZ + dt * TILE_M + tid] = s;
    }
}

// ---------------------------------------------------------------------------
// Kernel 2: softmax over D per batch. grid = B_SZ, block = 256. (R4 exact)
// ---------------------------------------------------------------------------
__global__ void softmax_kernel() {
    int b = blockIdx.x;
    int tid = threadIdx.x;
    __shared__ float red[256];

    float v[NCHUNK];
    float m = -1e30f;
    #pragma unroll
    for (int i = 0; i < NCHUNK; i++) {
        v[i] = g_scores[b * D_SZ + i * 256 + tid];
        m = fmaxf(m, v[i]);
    }
    red[tid] = m;
    __syncthreads();
    for (int s = 128; s > 0; s >>= 1) {
        if (tid < s) red[tid] = fmaxf(red[tid], red[tid + s]);
        __syncthreads();
    }
    m = red[0];
    __syncthreads();

    float ssum = 0.0f;
    #pragma unroll
    for (int i = 0; i < NCHUNK; i++) { v[i] = expf(v[i] - m); ssum += v[i]; }
    red[tid] = ssum;
    __syncthreads();
    for (int s = 128; s > 0; s >>= 1) {
        if (tid < s) red[tid] += red[tid + s];
        __syncthreads();
    }
    float inv = 1.0f / red[0];

    #pragma unroll
    for (int i = 0; i < NCHUNK; i++)
        g_scores[b * D_SZ + i * 256 + tid] = v[i] * inv;
}

// ---------------------------------------------------------------------------
// Kernel 3: weighted partial sums, 128-row chunks. grid=(16,B), block=256.
// (R4 exact)
// ---------------------------------------------------------------------------
__global__ void __launch_bounds__(256)
wsum_kernel(const float* __restrict__ Q) {
    int b = blockIdx.y;
    int c = blockIdx.x;       // 0..15
    int t = threadIdx.x;
    int h4 = t & 63;
    int sd = t >> 6;          // 0..3
    __shared__ float ws[128];
    if (t < 128) ws[t] = g_scores[b * D_SZ + c * 128 + t];
    __syncthreads();

    const float4* q = reinterpret_cast<const float4*>(
        Q + ((size_t)b * D_SZ + (size_t)c * 128 + (size_t)sd * 32) * H_SZ);
    const float* w = ws + sd * 32;
    float4 acc = make_float4(0.f, 0.f, 0.f, 0.f);
    #pragma unroll 8
    for (int i = 0; i < 32; i++) {
        float4 v = q[i * 64 + h4];
        float wv = w[i];
        acc.x = fmaf(wv, v.x, acc.x);
        acc.y = fmaf(wv, v.y, acc.y);
        acc.z = fmaf(wv, v.z, acc.z);
        acc.w = fmaf(wv, v.w, acc.w);
    }
    float4* dst = reinterpret_cast<float4*>(
        g_partial + ((size_t)b * 64 + (size_t)c * 4 + sd) * H_SZ);
    dst[h4] = acc;
}

// ---------------------------------------------------------------------------
// Kernel 4: reduce 64 partials -> out (B,1,H). grid = B_SZ, block = 256.
// (R4 exact)
// ---------------------------------------------------------------------------
__global__ void finalize_kernel(float* __restrict__ out) {
    int b = blockIdx.x;
    int h = threadIdx.x;
    float s = 0.0f;
    #pragma unroll
    for (int p = 0; p < 64; p++)
        s += g_partial[((size_t)b * 64 + p) * H_SZ + h];
    out[b * H_SZ + h] = s;
}

// ---------------------------------------------------------------------------
// Launch. Inputs: 0 context | 1 question | 2 hidden | 3 W1 | 4 W2 | 5 b2
//                 6 W3 | 7 W4 | 8 b4
// ---------------------------------------------------------------------------
extern "C" void kernel_launch(void* const* d_in, const int* in_sizes, int n_in,
                              void* d_out, int out_size) {
    const float* ctx = (const float*)d_in[0];
    const float* qn  = (const float*)d_in[1];
    const float* hid = (const float*)d_in[2];
    const float* W1  = (const float*)d_in[3];
    const float* W2  = (const float*)d_in[4];
    const float* b2  = (const float*)d_in[5];
    const float* W3  = (const float*)d_in[6];
    const float* W4  = (const float*)d_in[7];
    const float* b4  = (const float*)d_in[8];
    float* out = (float*)d_out;

    cudaFuncSetAttribute(gemm_score_bf16,
                         cudaFuncAttributeMaxDynamicSharedMemorySize, DYN_SMEM);

    prep_kernel<<<192, 256>>>(W1, ctx, hid, W2, b2, W3);
    gemm_score_bf16<<<dim3(NDT, B_SZ), 256, DYN_SMEM>>>(qn, W4, b4);
    softmax_kernel<<<B_SZ, 256>>>();
    wsum_kernel<<<dim3(16, B_SZ), 256>>>(qn);
    finalize_kernel<<<B_SZ, 256>>>(out);
}

// round 16
// speedup vs baseline: 1.3163x; 1.0618x over previous
#include <cuda_runtime.h>
#include <cuda_bf16.h>
#include <math.h>
#include <stdint.h>

// Problem constants
#define B_SZ 64
#define D_SZ 2048
#define H_SZ 256

// GEMM tiling: CTA = 128 M x 256 N x 256 K, bf16 fully resident in smem.
// 256 threads, 8 warps, warp tile 64x64.
#define TILE_M 128
#define NDT    (D_SZ / TILE_M)       // 16
#define ROWP   132                   // padded row stride in b32 (128 + 4)
#define A_B32  (TILE_M * ROWP)       // 16896
#define B_B32  (H_SZ * ROWP)         // 33792
#define DYN_SMEM ((A_B32 + B_B32) * 4)   // 202752 bytes

// Scratch (__device__ globals: allocation-free rule)
__device__ float    g_bias[B_SZ * H_SZ];
__device__ float    g_part[B_SZ * NDT * H_SZ];   // per-tile partial weighted sums
__device__ float    g_ml  [B_SZ * NDT * 2];      // per-tile (m_hat, l_hat)
__device__ uint32_t g_w1bf[H_SZ * H_SZ / 2];     // W1 as bf16x2 pairs

// ---------------- helpers ----------------
__device__ __forceinline__ uint32_t smem_u32(const void* p) {
    uint32_t a;
    asm("{ .reg .u64 t; cvta.to.shared.u64 t, %1; cvt.u32.u64 %0, t; }" : "=r"(a) : "l"(p));
    return a;
}
__device__ __forceinline__ float tanh_fast(float x) {
    float y;
    asm("tanh.approx.f32 %0, %1;" : "=f"(y) : "f"(x));
    return y;
}
__device__ __forceinline__ uint32_t pack_bf16(float lo, float hi) {
    uint32_t r;
    asm("cvt.rn.bf16x2.f32 %0, %1, %2;" : "=r"(r) : "f"(hi), "f"(lo));
    return r;
}
__device__ __forceinline__ void cp16(uint32_t dst, const void* src) {
    asm volatile("cp.async.cg.shared.global [%0], [%1], 16;" :: "r"(dst), "l"(src));
}
__device__ __forceinline__ void mma_bf16(float* d, const uint32_t* a, const uint32_t* b) {
    asm volatile(
        "mma.sync.aligned.m16n8k16.row.col.f32.bf16.bf16.f32 "
        "{%0,%1,%2,%3}, {%4,%5,%6,%7}, {%8,%9}, {%0,%1,%2,%3};"
        : "+f"(d[0]), "+f"(d[1]), "+f"(d[2]), "+f"(d[3])
        : "r"(a[0]), "r"(a[1]), "r"(a[2]), "r"(a[3]), "r"(b[0]), "r"(b[1]));
}

// ---------------------------------------------------------------------------
// Kernel 0: fused prep. Blocks 0..127: W1 fp32 -> bf16x2. Blocks 128..191:
// bias c[b][h] = W2@ctx + b2 + W3@hid.  grid = 192, block = 256.
// ---------------------------------------------------------------------------
__global__ void prep_kernel(const float* __restrict__ W1,
                            const float* __restrict__ ctx,
                            const float* __restrict__ hid,
                            const float* __restrict__ W2,
                            const float* __restrict__ b2,
                            const float* __restrict__ W3) {
    if (blockIdx.x < 128) {
        int i = blockIdx.x * 256 + threadIdx.x;
        float2 v = reinterpret_cast<const float2*>(W1)[i];
        g_w1bf[i] = pack_bf16(v.x, v.y);
        return;
    }
    int b = blockIdx.x - 128;
    int h = threadIdx.x;
    __shared__ float cs[H_SZ];
    __shared__ float hs[H_SZ];
    cs[h] = ctx[b * H_SZ + h];
    hs[h] = hid[b * H_SZ + h];
    __syncthreads();

    const float4* w2r = reinterpret_cast<const float4*>(W2 + (size_t)h * H_SZ);
    const float4* w3r = reinterpret_cast<const float4*>(W3 + (size_t)h * H_SZ);
    float acc = b2[h];
    #pragma unroll 8
    for (int k4 = 0; k4 < H_SZ / 4; k4++) {
        float4 a = w2r[k4], c = w3r[k4];
        int k = k4 * 4;
        acc += cs[k]*a.x + cs[k+1]*a.y + cs[k+2]*a.z + cs[k+3]*a.w;
        acc += hs[k]*c.x + hs[k+1]*c.y + hs[k+2]*c.z + hs[k+3]*c.w;
    }
    g_bias[b * H_SZ + h] = acc;
}

// ---------------------------------------------------------------------------
// Kernel 1: bf16 mma GEMM (Q @ W1^T) + tanh/W4 scores + FLASH-STYLE epilogue:
// per-tile local softmax stats (m_hat, l_hat) and partial weighted sum
// p[h] = sum_r exp(s_r - m_hat) * Q[r][h] (fp32 Q re-read, L2-hot).
// No global scores, no separate softmax/wsum kernels.
// 256 threads, 8 warps, warp tile 64x64 (R14 mainloop, measured at floor).
// ---------------------------------------------------------------------------
__global__ void __launch_bounds__(256, 1)
gemm_score_bf16(const float* __restrict__ Q,
                const float* __restrict__ W4,
                const float* __restrict__ b4) {
    extern __shared__ uint32_t sm[];
    uint32_t* As = sm;                 // [128][132] bf16x2
    uint32_t* Bs = sm + A_B32;         // [256][132] bf16x2
    __shared__ float cs[H_SZ];
    __shared__ float w4s[H_SZ];
    __shared__ float spart[TILE_M][4];
    __shared__ float ws[TILE_M];       // exp(s - m_hat) weights
    __shared__ float s_m, s_l;

    const int b    = blockIdx.y;
    const int dt   = blockIdx.x;
    const int tid  = threadIdx.x;
    const int wid  = tid >> 5;
    const int lane = tid & 31;
    const int wm   = wid >> 2;         // 0..1
    const int wn   = wid & 3;          // 0..3
    const int gq   = lane >> 2;        // 0..7
    const int tq   = lane & 3;         // 0..3

    cs[tid]  = g_bias[b * H_SZ + tid];
    w4s[tid] = W4[tid];

    // --- B (W1 bf16) via cp.async: 8192 16B chunks, 32 per thread ---
    {
        const uint32_t bbase = smem_u32(Bs);
        const char* src = reinterpret_cast<const char*>(g_w1bf);
        #pragma unroll
        for (int j = 0; j < 32; j++) {
            int idx = j * 256 + tid;
            int n = idx >> 5, c = idx & 31;
            cp16(bbase + (uint32_t)(n * ROWP + c * 4) * 4, src + n * 512 + c * 16);
        }
        asm volatile("cp.async.commit_group;" ::: "memory");
    }

    const float4* qg = reinterpret_cast<const float4*>(
        Q + ((size_t)b * D_SZ + (size_t)dt * TILE_M) * H_SZ);

    // --- A half0 (cols 0..127 fp32): 4096 f4, 16 per thread ---
    #pragma unroll
    for (int j = 0; j < 16; j++) {
        int idx = j * 256 + tid;
        int row = idx >> 5, c = idx & 31;
        float4 v = qg[row * 64 + c];
        uint32_t* d = As + row * ROWP + c * 2;
        d[0] = pack_bf16(v.x, v.y);
        d[1] = pack_bf16(v.z, v.w);
    }
    asm volatile("cp.async.wait_group 0;" ::: "memory");
    __syncthreads();                                // stage barrier 1

    float acc[4][8][4];
    #pragma unroll
    for (int i = 0; i < 4; i++)
        #pragma unroll
        for (int j = 0; j < 8; j++)
            #pragma unroll
            for (int r = 0; r < 4; r++) acc[i][j][r] = 0.0f;

    int aOff[4], bOff[8];
    #pragma unroll
    for (int ms = 0; ms < 4; ms++)
        aOff[ms] = (wm * 64 + ms * 16 + gq) * ROWP + tq;
    #pragma unroll
    for (int ns = 0; ns < 8; ns++)
        bOff[ns] = (wn * 64 + ns * 8 + gq) * ROWP + tq;

    #define K_STEP(k16) do {                                            \
        const int kb = (k16) * 8;                                       \
        uint32_t a[4][4], bb[8][2];                                     \
        _Pragma("unroll")                                               \
        for (int ms = 0; ms < 4; ms++) {                                \
            a[ms][0] = As[aOff[ms] + kb];                               \
            a[ms][1] = As[aOff[ms] + 8 * ROWP + kb];                    \
            a[ms][2] = As[aOff[ms] + kb + 4];                           \
            a[ms][3] = As[aOff[ms] + 8 * ROWP + kb + 4];                \
        }                                                               \
        _Pragma("unroll")                                               \
        for (int ns = 0; ns < 8; ns++) {                                \
            bb[ns][0] = Bs[bOff[ns] + kb];                              \
            bb[ns][1] = Bs[bOff[ns] + kb + 4];                          \
        }                                                               \
        _Pragma("unroll")                                               \
        for (int ms = 0; ms < 4; ms++)                                  \
            _Pragma("unroll")                                           \
            for (int ns = 0; ns < 8; ns++)                              \
                mma_bf16(acc[ms][ns], a[ms], bb[ns]);                   \
    } while (0)

    // --- half0 compute (k-steps 0..7), interleaved with A half1 prefetch ---
    #pragma unroll
    for (int g = 0; g < 4; g++) {
        float4 pf[4];
        int rowp[4], cp_[4];
        #pragma unroll
        for (int u = 0; u < 4; u++) {
            int idx = (g * 4 + u) * 256 + tid;
            rowp[u] = idx >> 5;
            cp_[u]  = idx & 31;
            pf[u] = qg[rowp[u] * 64 + 32 + cp_[u]];
        }
        K_STEP(2 * g);
        K_STEP(2 * g + 1);
        #pragma unroll
        for (int u = 0; u < 4; u++) {
            uint32_t* d = As + rowp[u] * ROWP + 64 + cp_[u] * 2;
            d[0] = pack_bf16(pf[u].x, pf[u].y);
            d[1] = pack_bf16(pf[u].z, pf[u].w);
        }
    }
    __syncthreads();                                // stage barrier 2

    #pragma unroll
    for (int k16 = 8; k16 < 16; k16++)
        K_STEP(k16);
    #undef K_STEP

    // --- scores: s[row] = b4 + sum_h tanh(v+c[h])*W4[h] ---
    #pragma unroll
    for (int ms = 0; ms < 4; ms++) {
        const int r0 = wm * 64 + ms * 16 + gq;
        const int r1 = r0 + 8;
        float sA = 0.0f, sB = 0.0f;
        #pragma unroll
        for (int ns = 0; ns < 8; ns++) {
            const int n0 = wn * 64 + ns * 8 + 2 * tq;
            const float w0 = w4s[n0], w1 = w4s[n0 + 1];
            const float c0 = cs[n0],  c1 = cs[n0 + 1];
            sA += tanh_fast(acc[ms][ns][0] + c0) * w0
                + tanh_fast(acc[ms][ns][1] + c1) * w1;
            sB += tanh_fast(acc[ms][ns][2] + c0) * w0
                + tanh_fast(acc[ms][ns][3] + c1) * w1;
        }
        sA += __shfl_xor_sync(0xffffffffu, sA, 1);
        sA += __shfl_xor_sync(0xffffffffu, sA, 2);
        sB += __shfl_xor_sync(0xffffffffu, sB, 1);
        sB += __shfl_xor_sync(0xffffffffu, sB, 2);
        if (tq == 0) {
            spart[r0][wn] = sA;
            spart[r1][wn] = sB;
        }
    }
    __syncthreads();

    // scores into ws (temporarily raw) via float scratch view of As region
    float* sscore = reinterpret_cast<float*>(sm);   // reuse (mainloop done)
    if (tid < TILE_M) {
        sscore[tid] = b4[0] + spart[tid][0] + spart[tid][1]
                            + spart[tid][2] + spart[tid][3];
    }
    __syncthreads();

    // local max over 128 scores
    if (tid < 32) {
        float m = fmaxf(fmaxf(sscore[tid], sscore[tid + 32]),
                        fmaxf(sscore[tid + 64], sscore[tid + 96]));
        #pragma unroll
        for (int o = 16; o > 0; o >>= 1)
            m = fmaxf(m, __shfl_xor_sync(0xffffffffu, m, o));
        if (lane == 0) s_m = m;
    }
    __syncthreads();
    if (tid < TILE_M) ws[tid] = expf(sscore[tid] - s_m);
    __syncthreads();
    if (tid < 32) {
        float l = ws[tid] + ws[tid + 32] + ws[tid + 64] + ws[tid + 96];
        #pragma unroll
        for (int o = 16; o > 0; o >>= 1)
            l += __shfl_xor_sync(0xffffffffu, l, o);
        if (lane == 0) s_l = l;
    }

    // --- partial weighted sum: p[h] = sum_r ws[r] * Q_fp32[r][h] ---
    // 4 row-groups of 32 (sd = tid>>6); thread handles float4 h4 = tid&63.
    const int h4 = tid & 63;
    const int sd = tid >> 6;
    const float4* qf = qg + (size_t)sd * 32 * 64;   // rows sd*32..+31
    const float* w = ws + sd * 32;
    float4 pa = make_float4(0.f, 0.f, 0.f, 0.f);
    #pragma unroll 8
    for (int i = 0; i < 32; i++) {
        float4 v = qf[i * 64 + h4];
        float wv = w[i];
        pa.x = fmaf(wv, v.x, pa.x);
        pa.y = fmaf(wv, v.y, pa.y);
        pa.z = fmaf(wv, v.z, pa.z);
        pa.w = fmaf(wv, v.w, pa.w);
    }
    float* red = sscore + 128;                      // 4*256 float scratch
    red[sd * 256 + h4 * 4 + 0] = pa.x;
    red[sd * 256 + h4 * 4 + 1] = pa.y;
    red[sd * 256 + h4 * 4 + 2] = pa.z;
    red[sd * 256 + h4 * 4 + 3] = pa.w;
    __syncthreads();

    float p = red[tid] + red[256 + tid] + red[512 + tid] + red[768 + tid];
    g_part[((size_t)b * NDT + dt) * H_SZ + tid] = p;
    if (tid == 0) {
        g_ml[(b * NDT + dt) * 2 + 0] = s_m;
        g_ml[(b * NDT + dt) * 2 + 1] = s_l;
    }
}

// ---------------------------------------------------------------------------
// Kernel 2: combine 16 tiles per batch (flash-style rescale) -> out (B,1,H).
// grid = B_SZ, block = 256. Deterministic fixed-order fp32.
// ---------------------------------------------------------------------------
__global__ void finalize_kernel(float* __restrict__ out) {
    int b = blockIdx.x;
    int t = threadIdx.x;
    __shared__ float tm[NDT], tl[NDT], sc[NDT];
    __shared__ float s_M, s_invL;

    if (t < NDT) {
        tm[t] = g_ml[(b * NDT + t) * 2 + 0];
        tl[t] = g_ml[(b * NDT + t) * 2 + 1];
    }
    __syncthreads();
    if (t == 0) {
        float M = tm[0];
        #pragma unroll
        for (int i = 1; i < NDT; i++) M = fmaxf(M, tm[i]);
        float L = 0.0f;
        #pragma unroll
        for (int i = 0; i < NDT; i++) {
            sc[i] = expf(tm[i] - M);
            L += tl[i] * sc[i];
        }
        s_M = M;
        s_invL = 1.0f / L;
    }
    __syncthreads();

    float s = 0.0f;
    #pragma unroll
    for (int i = 0; i < NDT; i++)
        s = fmaf(g_part[((size_t)b * NDT + i) * H_SZ + t], sc[i], s);
    out[b * H_SZ + t] = s * s_invL;
}

// ---------------------------------------------------------------------------
// Launch. Inputs: 0 context | 1 question | 2 hidden | 3 W1 | 4 W2 | 5 b2
//                 6 W3 | 7 W4 | 8 b4
// ---------------------------------------------------------------------------
extern "C" void kernel_launch(void* const* d_in, const int* in_sizes, int n_in,
                              void* d_out, int out_size) {
    const float* ctx = (const float*)d_in[0];
    const float* qn  = (const float*)d_in[1];
    const float* hid = (const float*)d_in[2];
    const float* W1  = (const float*)d_in[3];
    const float* W2  = (const float*)d_in[4];
    const float* b2  = (const float*)d_in[5];
    const float* W3  = (const float*)d_in[6];
    const float* W4  = (const float*)d_in[7];
    const float* b4  = (const float*)d_in[8];
    float* out = (float*)d_out;

    cudaFuncSetAttribute(gemm_score_bf16,
                         cudaFuncAttributeMaxDynamicSharedMemorySize, DYN_SMEM);

    prep_kernel<<<192, 256>>>(W1, ctx, hid, W2, b2, W3);
    gemm_score_bf16<<<dim3(NDT, B_SZ), 256, DYN_SMEM>>>(qn, W4, b4);
    finalize_kernel<<<B_SZ, 256>>>(out);
}

// round 17
// speedup vs baseline: 1.7356x; 1.3185x over previous
#include <cuda_runtime.h>
#include <cuda_bf16.h>
#include <math.h>
#include <stdint.h>

// Problem constants
#define B_SZ 64
#define D_SZ 2048
#define H_SZ 256

// GEMM tiling: CTA = 128 M x 256 N x 256 K, bf16 fully resident in smem.
// 256 threads, 8 warps, warp tile 64x64.
#define TILE_M 128
#define NDT    (D_SZ / TILE_M)       // 16
#define ROWP   132                   // padded row stride in b32 (128 + 4)
#define A_B32  (TILE_M * ROWP)       // 16896
#define B_B32  (H_SZ * ROWP)         // 33792
#define DYN_SMEM ((A_B32 + B_B32) * 4)   // 202752 bytes

// Scratch (__device__ globals: allocation-free rule)
__device__ float    g_bias[B_SZ * H_SZ];
__device__ float    g_part[B_SZ * NDT * H_SZ];   // per-tile partial weighted sums
__device__ float    g_ml  [B_SZ * NDT * 2];      // per-tile (m_hat, l_hat)
__device__ uint32_t g_w1bf[H_SZ * H_SZ / 2];     // W1 as bf16x2 pairs

// ---------------- helpers ----------------
__device__ __forceinline__ uint32_t smem_u32(const void* p) {
    uint32_t a;
    asm("{ .reg .u64 t; cvta.to.shared.u64 t, %1; cvt.u32.u64 %0, t; }" : "=r"(a) : "l"(p));
    return a;
}
__device__ __forceinline__ float tanh_fast(float x) {
    float y;
    asm("tanh.approx.f32 %0, %1;" : "=f"(y) : "f"(x));
    return y;
}
__device__ __forceinline__ uint32_t pack_bf16(float lo, float hi) {
    uint32_t r;
    asm("cvt.rn.bf16x2.f32 %0, %1, %2;" : "=r"(r) : "f"(hi), "f"(lo));
    return r;
}
__device__ __forceinline__ void cp16(uint32_t dst, const void* src) {
    asm volatile("cp.async.cg.shared.global [%0], [%1], 16;" :: "r"(dst), "l"(src));
}
__device__ __forceinline__ void mma_bf16(float* d, const uint32_t* a, const uint32_t* b) {
    asm volatile(
        "mma.sync.aligned.m16n8k16.row.col.f32.bf16.bf16.f32 "
        "{%0,%1,%2,%3}, {%4,%5,%6,%7}, {%8,%9}, {%0,%1,%2,%3};"
        : "+f"(d[0]), "+f"(d[1]), "+f"(d[2]), "+f"(d[3])
        : "r"(a[0]), "r"(a[1]), "r"(a[2]), "r"(a[3]), "r"(b[0]), "r"(b[1]));
}

// ---------------------------------------------------------------------------
// Kernel 0: fused prep.
// Blocks 0..127: W1 fp32 -> bf16x2 (coalesced, 1 float2/thread).
// Blocks 128..2175: bias, ONE WARP PER (b,h) output:
//   lanes split k -> W2/W3 row reads coalesced; shuffle-reduce the dot.
// grid = 2176, block = 256.
// ---------------------------------------------------------------------------
__global__ void prep_kernel(const float* __restrict__ W1,
                            const float* __restrict__ ctx,
                            const float* __restrict__ hid,
                            const float* __restrict__ W2,
                            const float* __restrict__ b2,
                            const float* __restrict__ W3) {
    if (blockIdx.x < 128) {
        int i = blockIdx.x * 256 + threadIdx.x;
        float2 v = reinterpret_cast<const float2*>(W1)[i];
        g_w1bf[i] = pack_bf16(v.x, v.y);
        return;
    }
    const int widx = (blockIdx.x - 128) * 8 + (threadIdx.x >> 5);  // 0..16383
    const int lane = threadIdx.x & 31;
    const int b = widx >> 8;        // batch
    const int h = widx & 255;       // output unit

    const float4* c4 = reinterpret_cast<const float4*>(ctx + (size_t)b * H_SZ);
    const float4* h4 = reinterpret_cast<const float4*>(hid + (size_t)b * H_SZ);
    const float4* w2 = reinterpret_cast<const float4*>(W2 + (size_t)h * H_SZ);
    const float4* w3 = reinterpret_cast<const float4*>(W3 + (size_t)h * H_SZ);

    float acc = 0.0f;
    #pragma unroll
    for (int i = 0; i < 2; i++) {
        int k4 = lane + 32 * i;     // 64 float4 per row
        float4 cv = c4[k4], wv = w2[k4];
        acc += cv.x*wv.x + cv.y*wv.y + cv.z*wv.z + cv.w*wv.w;
        float4 hv = h4[k4], uv = w3[k4];
        acc += hv.x*uv.x + hv.y*uv.y + hv.z*uv.z + hv.w*uv.w;
    }
    #pragma unroll
    for (int o = 16; o > 0; o >>= 1)
        acc += __shfl_xor_sync(0xffffffffu, acc, o);
    if (lane == 0)
        g_bias[b * H_SZ + h] = acc + b2[h];
}

// ---------------------------------------------------------------------------
// Kernel 1: bf16 mma GEMM (Q @ W1^T) + tanh/W4 scores + FLASH-STYLE epilogue:
// per-tile local softmax stats (m_hat, l_hat) and partial weighted sum
// p[h] = sum_r exp(s_r - m_hat) * Q[r][h] (fp32 Q re-read, L2-hot).
// 256 threads, 8 warps, warp tile 64x64.  (R16 exact — measured 138.8 total)
// ---------------------------------------------------------------------------
__global__ void __launch_bounds__(256, 1)
gemm_score_bf16(const float* __restrict__ Q,
                const float* __restrict__ W4,
                const float* __restrict__ b4) {
    extern __shared__ uint32_t sm[];
    uint32_t* As = sm;                 // [128][132] bf16x2
    uint32_t* Bs = sm + A_B32;         // [256][132] bf16x2
    __shared__ float cs[H_SZ];
    __shared__ float w4s[H_SZ];
    __shared__ float spart[TILE_M][4];
    __shared__ float ws[TILE_M];       // exp(s - m_hat) weights
    __shared__ float s_m, s_l;

    const int b    = blockIdx.y;
    const int dt   = blockIdx.x;
    const int tid  = threadIdx.x;
    const int wid  = tid >> 5;
    const int lane = tid & 31;
    const int wm   = wid >> 2;         // 0..1
    const int wn   = wid & 3;          // 0..3
    const int gq   = lane >> 2;        // 0..7
    const int tq   = lane & 3;         // 0..3

    cs[tid]  = g_bias[b * H_SZ + tid];
    w4s[tid] = W4[tid];

    // --- B (W1 bf16) via cp.async: 8192 16B chunks, 32 per thread ---
    {
        const uint32_t bbase = smem_u32(Bs);
        const char* src = reinterpret_cast<const char*>(g_w1bf);
        #pragma unroll
        for (int j = 0; j < 32; j++) {
            int idx = j * 256 + tid;
            int n = idx >> 5, c = idx & 31;
            cp16(bbase + (uint32_t)(n * ROWP + c * 4) * 4, src + n * 512 + c * 16);
        }
        asm volatile("cp.async.commit_group;" ::: "memory");
    }

    const float4* qg = reinterpret_cast<const float4*>(
        Q + ((size_t)b * D_SZ + (size_t)dt * TILE_M) * H_SZ);

    // --- A half0 (cols 0..127 fp32): 4096 f4, 16 per thread ---
    #pragma unroll
    for (int j = 0; j < 16; j++) {
        int idx = j * 256 + tid;
        int row = idx >> 5, c = idx & 31;
        float4 v = qg[row * 64 + c];
        uint32_t* d = As + row * ROWP + c * 2;
        d[0] = pack_bf16(v.x, v.y);
        d[1] = pack_bf16(v.z, v.w);
    }
    asm volatile("cp.async.wait_group 0;" ::: "memory");
    __syncthreads();                                // stage barrier 1

    float acc[4][8][4];
    #pragma unroll
    for (int i = 0; i < 4; i++)
        #pragma unroll
        for (int j = 0; j < 8; j++)
            #pragma unroll
            for (int r = 0; r < 4; r++) acc[i][j][r] = 0.0f;

    int aOff[4], bOff[8];
    #pragma unroll
    for (int ms = 0; ms < 4; ms++)
        aOff[ms] = (wm * 64 + ms * 16 + gq) * ROWP + tq;
    #pragma unroll
    for (int ns = 0; ns < 8; ns++)
        bOff[ns] = (wn * 64 + ns * 8 + gq) * ROWP + tq;

    #define K_STEP(k16) do {                                            \
        const int kb = (k16) * 8;                                       \
        uint32_t a[4][4], bb[8][2];                                     \
        _Pragma("unroll")                                               \
        for (int ms = 0; ms < 4; ms++) {                                \
            a[ms][0] = As[aOff[ms] + kb];                               \
            a[ms][1] = As[aOff[ms] + 8 * ROWP + kb];                    \
            a[ms][2] = As[aOff[ms] + kb + 4];                           \
            a[ms][3] = As[aOff[ms] + 8 * ROWP + kb + 4];                \
        }                                                               \
        _Pragma("unroll")                                               \
        for (int ns = 0; ns < 8; ns++) {                                \
            bb[ns][0] = Bs[bOff[ns] + kb];                              \
            bb[ns][1] = Bs[bOff[ns] + kb + 4];                          \
        }                                                               \
        _Pragma("unroll")                                               \
        for (int ms = 0; ms < 4; ms++)                                  \
            _Pragma("unroll")                                           \
            for (int ns = 0; ns < 8; ns++)                              \
                mma_bf16(acc[ms][ns], a[ms], bb[ns]);                   \
    } while (0)

    // --- half0 compute (k-steps 0..7), interleaved with A half1 prefetch ---
    #pragma unroll
    for (int g = 0; g < 4; g++) {
        float4 pf[4];
        int rowp[4], cp_[4];
        #pragma unroll
        for (int u = 0; u < 4; u++) {
            int idx = (g * 4 + u) * 256 + tid;
            rowp[u] = idx >> 5;
            cp_[u]  = idx & 31;
            pf[u] = qg[rowp[u] * 64 + 32 + cp_[u]];
        }
        K_STEP(2 * g);
        K_STEP(2 * g + 1);
        #pragma unroll
        for (int u = 0; u < 4; u++) {
            uint32_t* d = As + rowp[u] * ROWP + 64 + cp_[u] * 2;
            d[0] = pack_bf16(pf[u].x, pf[u].y);
            d[1] = pack_bf16(pf[u].z, pf[u].w);
        }
    }
    __syncthreads();                                // stage barrier 2

    #pragma unroll
    for (int k16 = 8; k16 < 16; k16++)
        K_STEP(k16);
    #undef K_STEP

    // --- scores: s[row] = b4 + sum_h tanh(v+c[h])*W4[h] ---
    #pragma unroll
    for (int ms = 0; ms < 4; ms++) {
        const int r0 = wm * 64 + ms * 16 + gq;
        const int r1 = r0 + 8;
        float sA = 0.0f, sB = 0.0f;
        #pragma unroll
        for (int ns = 0; ns < 8; ns++) {
            const int n0 = wn * 64 + ns * 8 + 2 * tq;
            const float w0 = w4s[n0], w1 = w4s[n0 + 1];
            const float c0 = cs[n0],  c1 = cs[n0 + 1];
            sA += tanh_fast(acc[ms][ns][0] + c0) * w0
                + tanh_fast(acc[ms][ns][1] + c1) * w1;
            sB += tanh_fast(acc[ms][ns][2] + c0) * w0
                + tanh_fast(acc[ms][ns][3] + c1) * w1;
        }
        sA += __shfl_xor_sync(0xffffffffu, sA, 1);
        sA += __shfl_xor_sync(0xffffffffu, sA, 2);
        sB += __shfl_xor_sync(0xffffffffu, sB, 1);
        sB += __shfl_xor_sync(0xffffffffu, sB, 2);
        if (tq == 0) {
            spart[r0][wn] = sA;
            spart[r1][wn] = sB;
        }
    }
    __syncthreads();

    // scores into shared scratch (reuse As region; mainloop done)
    float* sscore = reinterpret_cast<float*>(sm);
    if (tid < TILE_M) {
        sscore[tid] = b4[0] + spart[tid][0] + spart[tid][1]
                            + spart[tid][2] + spart[tid][3];
    }
    __syncthreads();

    // local max over 128 scores
    if (tid < 32) {
        float m = fmaxf(fmaxf(sscore[tid], sscore[tid + 32]),
                        fmaxf(sscore[tid + 64], sscore[tid + 96]));
        #pragma unroll
        for (int o = 16; o > 0; o >>= 1)
            m = fmaxf(m, __shfl_xor_sync(0xffffffffu, m, o));
        if (lane == 0) s_m = m;
    }
    __syncthreads();
    if (tid < TILE_M) ws[tid] = expf(sscore[tid] - s_m);
    __syncthreads();
    if (tid < 32) {
        float l = ws[tid] + ws[tid + 32] + ws[tid + 64] + ws[tid + 96];
        #pragma unroll
        for (int o = 16; o > 0; o >>= 1)
            l += __shfl_xor_sync(0xffffffffu, l, o);
        if (lane == 0) s_l = l;
    }

    // --- partial weighted sum: p[h] = sum_r ws[r] * Q_fp32[r][h] ---
    const int h4 = tid & 63;
    const int sd = tid >> 6;
    const float4* qf = qg + (size_t)sd * 32 * 64;   // rows sd*32..+31
    const float* w = ws + sd * 32;
    float4 pa = make_float4(0.f, 0.f, 0.f, 0.f);
    #pragma unroll 8
    for (int i = 0; i < 32; i++) {
        float4 v = qf[i * 64 + h4];
        float wv = w[i];
        pa.x = fmaf(wv, v.x, pa.x);
        pa.y = fmaf(wv, v.y, pa.y);
        pa.z = fmaf(wv, v.z, pa.z);
        pa.w = fmaf(wv, v.w, pa.w);
    }
    float* red = sscore + 128;                      // 4*256 float scratch
    red[sd * 256 + h4 * 4 + 0] = pa.x;
    red[sd * 256 + h4 * 4 + 1] = pa.y;
    red[sd * 256 + h4 * 4 + 2] = pa.z;
    red[sd * 256 + h4 * 4 + 3] = pa.w;
    __syncthreads();

    float p = red[tid] + red[256 + tid] + red[512 + tid] + red[768 + tid];
    g_part[((size_t)b * NDT + dt) * H_SZ + tid] = p;
    if (tid == 0) {
        g_ml[(b * NDT + dt) * 2 + 0] = s_m;
        g_ml[(b * NDT + dt) * 2 + 1] = s_l;
    }
}

// ---------------------------------------------------------------------------
// Kernel 2: combine 16 tiles per batch (flash-style rescale) -> out (B,1,H).
// grid = B_SZ, block = 256. Deterministic fixed-order fp32.
// ---------------------------------------------------------------------------
__global__ void finalize_kernel(float* __restrict__ out) {
    int b = blockIdx.x;
    int t = threadIdx.x;
    __shared__ float tm[NDT], tl[NDT], sc[NDT];
    __shared__ float s_M, s_invL;

    if (t < NDT) {
        tm[t] = g_ml[(b * NDT + t) * 2 + 0];
        tl[t] = g_ml[(b * NDT + t) * 2 + 1];
    }
    __syncthreads();
    if (t == 0) {
        float M = tm[0];
        #pragma unroll
        for (int i = 1; i < NDT; i++) M = fmaxf(M, tm[i]);
        float L = 0.0f;
        #pragma unroll
        for (int i = 0; i < NDT; i++) {
            sc[i] = expf(tm[i] - M);
            L += tl[i] * sc[i];
        }
        s_M = M;
        s_invL = 1.0f / L;
    }
    __syncthreads();

    float s = 0.0f;
    #pragma unroll
    for (int i = 0; i < NDT; i++)
        s = fmaf(g_part[((size_t)b * NDT + i) * H_SZ + t], sc[i], s);
    out[b * H_SZ + t] = s * s_invL;
}

// ---------------------------------------------------------------------------
// Launch. Inputs: 0 context | 1 question | 2 hidden | 3 W1 | 4 W2 | 5 b2
//                 6 W3 | 7 W4 | 8 b4
// ---------------------------------------------------------------------------
extern "C" void kernel_launch(void* const* d_in, const int* in_sizes, int n_in,
                              void* d_out, int out_size) {
    const float* ctx = (const float*)d_in[0];
    const float* qn  = (const float*)d_in[1];
    const float* hid = (const float*)d_in[2];
    const float* W1  = (const float*)d_in[3];
    const float* W2  = (const float*)d_in[4];
    const float* b2  = (const float*)d_in[5];
    const float* W3  = (const float*)d_in[6];
    const float* W4  = (const float*)d_in[7];
    const float* b4  = (const float*)d_in[8];
    float* out = (float*)d_out;

    cudaFuncSetAttribute(gemm_score_bf16,
                         cudaFuncAttributeMaxDynamicSharedMemorySize, DYN_SMEM);

    prep_kernel<<<2176, 256>>>(W1, ctx, hid, W2, b2, W3);
    gemm_score_bf16<<<dim3(NDT, B_SZ), 256, DYN_SMEM>>>(qn, W4, b4);
    finalize_kernel<<<B_SZ, 256>>>(out);
}